// round 1
// baseline (speedup 1.0000x reference)
#include <cuda_runtime.h>
#include <math.h>

#define TSEQ   2048
#define NH     16
#define DNOPE  128
#define DROPE  64
#define DQK    192
#define DLORA  512
#define DV     128
// 1/sqrt(192)
#define SCALE  0.07216878364870323f

// 16 MB scratch for k_nope[t][h][d]  (device global: allocation-free)
__device__ float g_knope[(size_t)TSEQ * NH * DNOPE];

// ---------------------------------------------------------------------------
// Kernel 1: k_nope[t, h, d] = sum_l k_c[t, l] * w_kv_b[l, h*256 + d], d<128
// M=2048, N=2048 (h*128+d), K=512.  128x128 CTA tile, 8x8 per thread.
// ---------------------------------------------------------------------------
__global__ __launch_bounds__(256) void knope_gemm(const float* __restrict__ kc,
                                                  const float* __restrict__ wkv) {
    __shared__ float sA[16][132];  // [k][m] transposed
    __shared__ float sB[16][132];  // [k][n]
    const int bx = blockIdx.x;     // head (n tile of 128)
    const int by = blockIdx.y;     // m tile of 128
    const int tid = threadIdx.x;
    const int tm = tid >> 4, tn = tid & 15;
    const int m0 = tm * 8, n0 = tn * 8;

    float acc[8][8];
#pragma unroll
    for (int i = 0; i < 8; i++)
#pragma unroll
        for (int j = 0; j < 8; j++) acc[i][j] = 0.f;

    for (int k0 = 0; k0 < DLORA; k0 += 16) {
        // A: 128 rows x 16 k  (512 float4), store transposed
#pragma unroll
        for (int t = 0; t < 2; t++) {
            int idx = tid + t * 256;
            int r = idx >> 2, c4 = idx & 3;
            float4 v = *(const float4*)(kc + (size_t)(by * 128 + r) * DLORA + k0 + c4 * 4);
            sA[c4 * 4 + 0][r] = v.x;
            sA[c4 * 4 + 1][r] = v.y;
            sA[c4 * 4 + 2][r] = v.z;
            sA[c4 * 4 + 3][r] = v.w;
        }
        // B: 16 k-rows x 128 cols (contiguous inside head block bx)
#pragma unroll
        for (int t = 0; t < 2; t++) {
            int idx = tid + t * 256;
            int r = idx >> 5, c4 = idx & 31;
            float4 v = *(const float4*)(wkv + (size_t)(k0 + r) * 4096 + bx * 256 + c4 * 4);
            *(float4*)(&sB[r][c4 * 4]) = v;
        }
        __syncthreads();
#pragma unroll
        for (int k = 0; k < 16; k++) {
            float4 a0 = *(float4*)&sA[k][m0];
            float4 a1 = *(float4*)&sA[k][m0 + 4];
            float4 b0 = *(float4*)&sB[k][n0];
            float4 b1 = *(float4*)&sB[k][n0 + 4];
            float av[8] = {a0.x, a0.y, a0.z, a0.w, a1.x, a1.y, a1.z, a1.w};
            float bv[8] = {b0.x, b0.y, b0.z, b0.w, b1.x, b1.y, b1.z, b1.w};
#pragma unroll
            for (int i = 0; i < 8; i++)
#pragma unroll
                for (int j = 0; j < 8; j++) acc[i][j] += av[i] * bv[j];
        }
        __syncthreads();
    }
#pragma unroll
    for (int i = 0; i < 8; i++) {
        float* dst = g_knope + (size_t)(by * 128 + m0 + i) * (NH * DNOPE) + bx * DNOPE + n0;
        *(float4*)dst = make_float4(acc[i][0], acc[i][1], acc[i][2], acc[i][3]);
        *(float4*)(dst + 4) = make_float4(acc[i][4], acc[i][5], acc[i][6], acc[i][7]);
    }
}

// ---------------------------------------------------------------------------
// Kernel 2: fused causal attention per (head, 64-row q tile).
//   pass 1: running rowmax / rowsum over key tiles (BN=32)
//   pass 2: P = exp(s-m)*inv_sum, latent O(64x512) += P @ Kc  (O in SMEM)
//   epilogue: out(64x128) = O @ w_uv[h]
// Thread map for S: 16 m-groups x 16 n-groups, 4m x 2n per thread.
// Thread map for PV/proj: 16 m-groups x 16 l/v-groups, 4 x 8 per thread.
// ---------------------------------------------------------------------------
__device__ __forceinline__ void compute_s(const float* __restrict__ sQ,
                                          const float* __restrict__ sK,
                                          int m0, int n0, int rq, int rk,
                                          float acc[4][2]) {
#pragma unroll
    for (int i = 0; i < 4; i++) { acc[i][0] = 0.f; acc[i][1] = 0.f; }
#pragma unroll 8
    for (int c4 = 0; c4 < 48; c4++) {
        int pq = ((c4 & ~7) | ((c4 ^ rq) & 7)) * 4;
        int pk = ((c4 & ~7) | ((c4 ^ rk) & 7)) * 4;
        float4 k0v = *(const float4*)(sK + (n0 + 0) * 192 + pk);
        float4 k1v = *(const float4*)(sK + (n0 + 1) * 192 + pk);
#pragma unroll
        for (int i = 0; i < 4; i++) {
            float4 qv = *(const float4*)(sQ + (m0 + i) * 192 + pq);
            acc[i][0] += qv.x * k0v.x + qv.y * k0v.y + qv.z * k0v.z + qv.w * k0v.w;
            acc[i][1] += qv.x * k1v.x + qv.y * k1v.y + qv.z * k1v.z + qv.w * k1v.w;
        }
    }
}

__global__ __launch_bounds__(256) void mla_attn(const float* __restrict__ q,
                                                const float* __restrict__ kc,
                                                const float* __restrict__ kpe,
                                                const float* __restrict__ wuv,
                                                float* __restrict__ out) {
    extern __shared__ float smem[];
    float* sQ = smem;                    // 64*192 = 12288 (swizzled)
    float* sK = sQ + 64 * 192;           // 32*192 = 6144 (reused as Kc/W chunk 32*132)
    float* sP = sK + 32 * 192;           // 64*36  = 2304
    float* sO = sP + 64 * 36;            // 64*516 = 33024

    const int qt = blockIdx.x, h = blockIdx.y;
    const int tid = threadIdx.x;
    const int tm = tid >> 4, tn = tid & 15;
    const int m0 = tm * 4, n0 = tn * 2;
    const int rq = tm, rk = tn >> 1;

    // load Q tile (swizzled), zero O accumulator
    for (int idx = tid; idx < 64 * 48; idx += 256) {
        int r = idx / 48, c4 = idx % 48;
        float4 v = *(const float4*)(q + (size_t)(qt * 64 + r) * (NH * DQK) + h * DQK + c4 * 4);
        int p = (c4 & ~7) | ((c4 ^ (r >> 2)) & 7);
        *(float4*)(sQ + r * 192 + p * 4) = v;
    }
    for (int idx = tid; idx < 64 * 516; idx += 256) sO[idx] = 0.f;
    __syncthreads();

    const int jmax = 2 * qt + 1;
    float m_run[4], s_run[4];
#pragma unroll
    for (int i = 0; i < 4; i++) { m_run[i] = -INFINITY; s_run[i] = 0.f; }

    // ---------------- PASS 1: softmax statistics ----------------
    for (int j = 0; j <= jmax; j++) {
        for (int idx = tid; idx < 32 * 48; idx += 256) {
            int r = idx / 48, c4 = idx % 48;
            int s = j * 32 + r;
            float4 v;
            if (c4 < 32) v = *(const float4*)(g_knope + (size_t)s * (NH * DNOPE) + h * DNOPE + c4 * 4);
            else         v = *(const float4*)(kpe + (size_t)s * DROPE + (c4 - 32) * 4);
            int p = (c4 & ~7) | ((c4 ^ (r >> 2)) & 7);
            *(float4*)(sK + r * 192 + p * 4) = v;
        }
        __syncthreads();

        float acc[4][2];
        compute_s(sQ, sK, m0, n0, rq, rk, acc);

#pragma unroll
        for (int i = 0; i < 4; i++) {
            int gm = qt * 64 + m0 + i;
            float s0 = (j * 32 + n0 + 0 <= gm) ? acc[i][0] * SCALE : -INFINITY;
            float s1 = (j * 32 + n0 + 1 <= gm) ? acc[i][1] * SCALE : -INFINITY;
            float tmax = fmaxf(s0, s1);
#pragma unroll
            for (int d = 1; d < 16; d <<= 1)
                tmax = fmaxf(tmax, __shfl_xor_sync(0xffffffffu, tmax, d));
            float mnew = fmaxf(m_run[i], tmax);        // finite for all rows from j=0
            float psum = __expf(s0 - mnew) + __expf(s1 - mnew);  // exp(-inf)=0 masks
#pragma unroll
            for (int d = 1; d < 16; d <<= 1)
                psum += __shfl_xor_sync(0xffffffffu, psum, d);
            float alpha = __expf(m_run[i] - mnew);
            s_run[i] = s_run[i] * alpha + psum;
            m_run[i] = mnew;
        }
        __syncthreads();
    }
    float inv[4];
#pragma unroll
    for (int i = 0; i < 4; i++) inv[i] = 1.f / s_run[i];

    // ---------------- PASS 2: P and latent accumulation ----------------
    const int lo = tn * 8;
    for (int j = 0; j <= jmax; j++) {
        for (int idx = tid; idx < 32 * 48; idx += 256) {
            int r = idx / 48, c4 = idx % 48;
            int s = j * 32 + r;
            float4 v;
            if (c4 < 32) v = *(const float4*)(g_knope + (size_t)s * (NH * DNOPE) + h * DNOPE + c4 * 4);
            else         v = *(const float4*)(kpe + (size_t)s * DROPE + (c4 - 32) * 4);
            int p = (c4 & ~7) | ((c4 ^ (r >> 2)) & 7);
            *(float4*)(sK + r * 192 + p * 4) = v;
        }
        __syncthreads();

        float acc[4][2];
        compute_s(sQ, sK, m0, n0, rq, rk, acc);

#pragma unroll
        for (int i = 0; i < 4; i++) {
            int gm = qt * 64 + m0 + i;
#pragma unroll
            for (int jj = 0; jj < 2; jj++) {
                int gn = j * 32 + n0 + jj;
                float s = (gn <= gm) ? acc[i][jj] * SCALE : -INFINITY;
                sP[(m0 + i) * 36 + n0 + jj] = __expf(s - m_run[i]) * inv[i];
            }
        }
        __syncthreads();   // P visible; sK free to be overwritten

#pragma unroll
        for (int lc = 0; lc < 4; lc++) {
            for (int idx = tid; idx < 1024; idx += 256) {
                int r = idx >> 5, c4 = idx & 31;
                *(float4*)(sK + r * 132 + c4 * 4) =
                    *(const float4*)(kc + (size_t)(j * 32 + r) * DLORA + lc * 128 + c4 * 4);
            }
            __syncthreads();

            float a[4][8];
#pragma unroll
            for (int i = 0; i < 4; i++)
#pragma unroll
                for (int v = 0; v < 8; v++) a[i][v] = 0.f;

#pragma unroll 4
            for (int n = 0; n < 32; n++) {
                float4 c0 = *(const float4*)(sK + n * 132 + lo);
                float4 c1 = *(const float4*)(sK + n * 132 + lo + 4);
                float cv[8] = {c0.x, c0.y, c0.z, c0.w, c1.x, c1.y, c1.z, c1.w};
#pragma unroll
                for (int i = 0; i < 4; i++) {
                    float p = sP[(m0 + i) * 36 + n];
#pragma unroll
                    for (int v = 0; v < 8; v++) a[i][v] += p * cv[v];
                }
            }
#pragma unroll
            for (int i = 0; i < 4; i++) {
                float* o = sO + (m0 + i) * 516 + lc * 128 + lo;
                float4 o0 = *(float4*)o, o1 = *(float4*)(o + 4);
                o0.x += a[i][0]; o0.y += a[i][1]; o0.z += a[i][2]; o0.w += a[i][3];
                o1.x += a[i][4]; o1.y += a[i][5]; o1.z += a[i][6]; o1.w += a[i][7];
                *(float4*)o = o0; *(float4*)(o + 4) = o1;
            }
            __syncthreads();
        }
    }

    // ---------------- epilogue: out = O @ w_uv[h] ----------------
    float a2[4][8];
#pragma unroll
    for (int i = 0; i < 4; i++)
#pragma unroll
        for (int v = 0; v < 8; v++) a2[i][v] = 0.f;

    for (int l0 = 0; l0 < DLORA; l0 += 32) {
        for (int idx = tid; idx < 1024; idx += 256) {
            int r = idx >> 5, c4 = idx & 31;
            *(float4*)(sK + r * 132 + c4 * 4) =
                *(const float4*)(wuv + (size_t)h * DLORA * DV + (size_t)(l0 + r) * DV + c4 * 4);
        }
        __syncthreads();
#pragma unroll 4
        for (int l = 0; l < 32; l++) {
            float4 w0 = *(const float4*)(sK + l * 132 + lo);
            float4 w1 = *(const float4*)(sK + l * 132 + lo + 4);
            float wv[8] = {w0.x, w0.y, w0.z, w0.w, w1.x, w1.y, w1.z, w1.w};
#pragma unroll
            for (int i = 0; i < 4; i++) {
                float ov = sO[(m0 + i) * 516 + l0 + l];
#pragma unroll
                for (int v = 0; v < 8; v++) a2[i][v] += ov * wv[v];
            }
        }
        __syncthreads();
    }
#pragma unroll
    for (int i = 0; i < 4; i++) {
        float* dst = out + (size_t)(qt * 64 + m0 + i) * (NH * DV) + h * DV + lo;
        *(float4*)dst = make_float4(a2[i][0], a2[i][1], a2[i][2], a2[i][3]);
        *(float4*)(dst + 4) = make_float4(a2[i][4], a2[i][5], a2[i][6], a2[i][7]);
    }
}

// ---------------------------------------------------------------------------
extern "C" void kernel_launch(void* const* d_in, const int* in_sizes, int n_in,
                              void* d_out, int out_size) {
    (void)in_sizes; (void)n_in; (void)out_size;
    const float* q   = (const float*)d_in[0];   // (T, H, 192)
    const float* kc  = (const float*)d_in[1];   // (T, 512)
    const float* kpe = (const float*)d_in[2];   // (T, 64)
    const float* wkv = (const float*)d_in[3];   // (512, 4096)
    const float* wuv = (const float*)d_in[4];   // (16, 512, 128)
    float* out = (float*)d_out;                 // (T, 2048)

    knope_gemm<<<dim3(16, 16), 256>>>(kc, wkv);

    const int smem_bytes = (64 * 192 + 32 * 192 + 64 * 36 + 64 * 516) * 4;  // 215040
    cudaFuncSetAttribute(mla_attn, cudaFuncAttributeMaxDynamicSharedMemorySize, smem_bytes);
    mla_attn<<<dim3(32, 16), 256, smem_bytes>>>(q, kc, kpe, wuv, out);
}